// round 13
// baseline (speedup 1.0000x reference)
#include <cuda_runtime.h>
#include <cuda_fp16.h>
#include <cstdint>

#define B_NODES 8192
#define ZS      10
#define INC     512
#define OUTC    512
#define MD      3
#define ALPHA   0.04419417382415922f   // 1/sqrt(512)

#define NT      64
#define NCOLS   (NT*MD)                // 192
#define CT      64                     // C tile (2 CTAs/SM)
#define KT      64                     // k halves per stage
#define KSTAGES (INC/KT)               // 8
#define NSLOTS  3
#define NTHREADS 256
#define TILES   138

#define A_BYTES     (CT*KT*2)          // 8192  (64 rows x 128B)
#define B_BYTES     (NCOLS*KT*2)       // 24576 (192 rows x 128B)
#define STAGE_BYTES (A_BYTES+B_BYTES)  // 32768
#define GEMM_SMEM   (NSLOTS*STAGE_BYTES) // 98304
#define OSTR 196                       // epilogue smem row stride (floats)

#define SHB2 204                       // pack smem row stride (halves; 102 words ≡ 2 mod 4)
#define PACK_SMEM (NT*SHB2*2)          // 26112

// --------- scratch ----------
__device__ int g_tilez[TILES];
__device__ int g_psorted[TILES * NT];
__device__ int g_species[B_NODES];
__device__ int g_cursor[ZS];
__device__ __half Wh[(size_t)ZS * OUTC * INC];       // [z][c][k] fp16
__device__ __half Bh[(size_t)TILES * NCOLS * INC];   // [tile][n][k] fp16

// --------- helpers ----------
__device__ __forceinline__ void cpa16(void* dst, const void* src) {
    uint32_t d = (uint32_t)__cvta_generic_to_shared(dst);
    asm volatile("cp.async.cg.shared.global [%0], [%1], 16;" :: "r"(d), "l"(src) : "memory");
}
#define LDSM_X4(r, a) \
    asm volatile("ldmatrix.sync.aligned.m8n8.x4.shared.b16 {%0,%1,%2,%3}, [%4];" \
        : "=r"((r)[0]), "=r"((r)[1]), "=r"((r)[2]), "=r"((r)[3]) : "r"(a))

__device__ __forceinline__ void mma_f16(float* c, const uint32_t* a, const uint32_t* b) {
    asm volatile(
        "mma.sync.aligned.m16n8k16.row.col.f32.f16.f16.f32 "
        "{%0,%1,%2,%3}, {%4,%5,%6,%7}, {%8,%9}, {%0,%1,%2,%3};"
        : "+f"(c[0]), "+f"(c[1]), "+f"(c[2]), "+f"(c[3])
        : "r"(a[0]), "r"(a[1]), "r"(a[2]), "r"(a[3]), "r"(b[0]), "r"(b[1]));
}

// --------- prep stage 1: classify (16 blocks, coalesced) ----------
__global__ __launch_bounds__(512)
void k_classify(const float* __restrict__ attrs)
{
    __shared__ float buf[512 * ZS];
    const int tid = threadIdx.x;
    const float4* src = (const float4*)attrs + (size_t)blockIdx.x * 1280;
    float4* d = (float4*)buf;
#pragma unroll
    for (int i = 0; i < 3; i++) {
        int idx = i * 512 + tid;
        if (idx < 1280) d[idx] = src[idx];
    }
    __syncthreads();
    int s = 0;
#pragma unroll
    for (int z = 0; z < ZS; z++)
        s = (buf[tid * ZS + z] > 0.5f) ? z : s;
    g_species[blockIdx.x * 512 + tid] = s;
}

// --------- prep stage 2: hist + scan + tile table + sentinel fill ----------
__global__ __launch_bounds__(1024)
void k_scan()
{
    __shared__ int hist[ZS];
    const int tid = threadIdx.x;
    const int lane = tid & 31;
    if (tid < ZS) hist[tid] = 0;
    __syncthreads();
#pragma unroll
    for (int j = 0; j < 8; j++) {
        int s = g_species[j * 1024 + tid];
        unsigned m = __match_any_sync(0xffffffffu, s);
        if (lane == __ffs(m) - 1) atomicAdd(&hist[s], __popc(m));
    }
    __syncthreads();
    if (tid == 0) {
        int acc = 0;
        for (int z = 0; z < ZS; z++) {
            g_cursor[z] = acc;
            int tiles = (hist[z] + NT - 1) / NT;
            for (int ti = 0; ti < tiles; ti++) g_tilez[acc / NT + ti] = z;
            acc += tiles * NT;
        }
        for (int ti = acc / NT; ti < TILES; ti++) g_tilez[ti] = -1;
    }
    for (int i = tid; i < TILES * NT; i += 1024) g_psorted[i] = -1;
}

// --------- prep stage 3: scatter (16 blocks, hierarchical rank) ----------
__global__ __launch_bounds__(512)
void k_scatter()
{
    __shared__ int blkcnt[ZS], blkbase[ZS];
    const int tid = threadIdx.x;
    const int lane = tid & 31;
    if (tid < ZS) blkcnt[tid] = 0;
    __syncthreads();

    const int b = blockIdx.x * 512 + tid;
    const int s = g_species[b];
    unsigned m = __match_any_sync(0xffffffffu, s);
    int leader = __ffs(m) - 1;
    int gbase = 0;
    if (lane == leader) gbase = atomicAdd(&blkcnt[s], __popc(m));
    gbase = __shfl_sync(m, gbase, leader);
    const int rank = gbase + __popc(m & ((1u << lane) - 1));
    __syncthreads();

    if (tid < ZS && blkcnt[tid] > 0)
        blkbase[tid] = atomicAdd(&g_cursor[tid], blkcnt[tid]);
    __syncthreads();

    g_psorted[blkbase[s] + rank] = b;
}

// --------- fused pack: Bh (gather/convert/transpose, fp16 staging) + Wh ----------
__global__ void k_pack(const float* __restrict__ t, const float* __restrict__ W) {
    int bx = blockIdx.x;
    int tid = threadIdx.x;

    if (bx >= TILES) {
        // ---- W -> fp16 chunk ----
        int c = (bx - TILES) * 8 + blockIdx.y;           // 0..1279
        size_t i = ((size_t)c * 256 + tid) * 8;
        float4 v0 = *(const float4*)(W + i);
        float4 v1 = *(const float4*)(W + i + 4);
        __half2 h[4];
        h[0] = __floats2half2_rn(v0.x, v0.y);
        h[1] = __floats2half2_rn(v0.z, v0.w);
        h[2] = __floats2half2_rn(v1.x, v1.y);
        h[3] = __floats2half2_rn(v1.z, v1.w);
        *(uint4*)(Wh + i) = *(uint4*)h;
        return;
    }

    int tile = bx;
    if (g_tilez[tile] < 0) return;
    int kc = blockIdx.y;                     // 64-k chunk
    extern __shared__ __half sh2[];          // [64 nodes][204] halves
#pragma unroll
    for (int i = 0; i < 12; i++) {
        int idx = i * 256 + tid;             // 3072 float4s
        int nl = idx / 48, f4 = idx % 48;
        int node = g_psorted[tile * NT + nl];
        float4 v = make_float4(0.f, 0.f, 0.f, 0.f);
        if (node >= 0)
            v = *(const float4*)(t + (size_t)node * (INC * MD) + kc * 192 + f4 * 4);
        __half2 p[2];
        p[0] = __floats2half2_rn(v.x, v.y);
        p[1] = __floats2half2_rn(v.z, v.w);
        *(uint2*)(sh2 + nl * SHB2 + f4 * 4) = *(uint2*)p;
    }
    __syncthreads();
    __half* dst = Bh + (size_t)tile * NCOLS * INC + kc * 64;
#pragma unroll
    for (int i = 0; i < 6; i++) {
        int idx = i * 256 + tid;             // 1536 = 192 n-rows x 8 k-octs
        int n = idx >> 3, k8 = idx & 7;
        int nl = n / 3, d = n % 3;
        __half q[8];
#pragma unroll
        for (int e = 0; e < 8; e++)
            q[e] = sh2[nl * SHB2 + (k8 * 8 + e) * 3 + d];
        *(uint4*)(dst + (size_t)n * INC + k8 * 8) = *(uint4*)q;
    }
}

// --------- GEMM: CT=64, 256 thr, 2 CTAs/SM, cp.async ring + ldmatrix + fp16 mma ----------
__global__ __launch_bounds__(NTHREADS, 2)
void k_gemm(float* __restrict__ out)
{
    const int tile = blockIdx.x;
    const int z = g_tilez[tile];
    if (z < 0) return;
    const int c0 = blockIdx.y * CT;

    extern __shared__ float sm[];
    char* smc = (char*)sm;
    __shared__ int nodes_s[NT];

    const int tid = threadIdx.x;
    if (tid < NT) nodes_s[tid] = g_psorted[tile * NT + tid];

    const int lane = tid & 31;
    const int wid  = tid >> 5;
    const int wm   = wid & 1;              // 2 M groups (32 rows)
    const int wn   = wid >> 1;             // 4 N groups (48 cols)
    const int g    = lane >> 2;
    const int tg   = lane & 3;

    const __half* abase = Wh + ((size_t)z * OUTC + c0) * INC;
    const __half* bbase = Bh + (size_t)tile * NCOLS * INC;

    // per stage: A 512 16B-chunks (64 rows x 8), B 1536 (192 rows x 8)
    auto issue = [&](int s) {
        char* ab = smc + (s % NSLOTS) * STAGE_BYTES;
        const __half* asrc = abase + s * KT;
#pragma unroll
        for (int i = 0; i < 2; i++) {
            int idx = i * NTHREADS + tid;
            int m = idx >> 3, c = idx & 7;
            cpa16(ab + m * 128 + ((c ^ (m & 7)) << 4),
                  asrc + (size_t)m * INC + c * 8);
        }
        char* bb = ab + A_BYTES;
        const __half* bsrc = bbase + s * KT;
#pragma unroll
        for (int i = 0; i < 6; i++) {
            int idx = i * NTHREADS + tid;
            int n = idx >> 3, c = idx & 7;
            cpa16(bb + n * 128 + ((c ^ (n & 7)) << 4),
                  bsrc + (size_t)n * INC + c * 8);
        }
    };

    issue(0); asm volatile("cp.async.commit_group;" ::: "memory");
    issue(1); asm volatile("cp.async.commit_group;" ::: "memory");

    // ---- per-lane ldmatrix addressing ----
    const int mi = lane >> 3;
    const int mr = lane & 7;
    uint32_t aoff[2], a7[2];
#pragma unroll
    for (int mt = 0; mt < 2; mt++) {
        int m = wm * 32 + mt * 16 + (mi & 1) * 8 + mr;
        aoff[mt] = (uint32_t)m * 128;
        a7[mt] = (uint32_t)(m & 7);
    }
    const uint32_t akc = (uint32_t)(mi >> 1);
    uint32_t boff[3], b7[3];
#pragma unroll
    for (int p = 0; p < 3; p++) {
        int n = wn * 48 + p * 16 + (mi >> 1) * 8 + mr;
        boff[p] = (uint32_t)n * 128;
        b7[p] = (uint32_t)(n & 7);
    }
    const uint32_t bkc = (uint32_t)(mi & 1);
    const uint32_t smbase = (uint32_t)__cvta_generic_to_shared(sm);

    float acc[2][6][4];
#pragma unroll
    for (int i = 0; i < 2; i++)
#pragma unroll
        for (int j = 0; j < 6; j++)
#pragma unroll
            for (int e = 0; e < 4; e++) acc[i][j][e] = 0.f;

    for (int s = 0; s < KSTAGES; s++) {
        asm volatile("cp.async.wait_group 1;" ::: "memory");
        __syncthreads();
        if (s + 2 < KSTAGES) issue(s + 2);
        asm volatile("cp.async.commit_group;" ::: "memory");

        const uint32_t sA = smbase + (s % NSLOTS) * STAGE_BYTES;
        const uint32_t sB = sA + A_BYTES;
#pragma unroll
        for (int kc = 0; kc < 4; kc++) {
            uint32_t a[2][4];
#pragma unroll
            for (int mt = 0; mt < 2; mt++)
                LDSM_X4(a[mt], sA + aoff[mt] + (((((uint32_t)kc << 1) + akc) ^ a7[mt]) << 4));
            uint32_t b[3][4];
#pragma unroll
            for (int p = 0; p < 3; p++)
                LDSM_X4(b[p], sB + boff[p] + (((((uint32_t)kc << 1) + bkc) ^ b7[p]) << 4));
#pragma unroll
            for (int mt = 0; mt < 2; mt++)
#pragma unroll
                for (int nt = 0; nt < 6; nt++)
                    mma_f16(acc[mt][nt], a[mt], b[nt >> 1] + (nt & 1) * 2);
        }
    }

    // ---- epilogue: acc -> smem [node][C*3+d] (64x196 floats) -> coalesced out ----
    __syncthreads();
#pragma unroll
    for (int mt = 0; mt < 2; mt++) {
#pragma unroll
        for (int nt = 0; nt < 6; nt++) {
#pragma unroll
            for (int e = 0; e < 4; e++) {
                int Cl = wm * 32 + mt * 16 + g + (e >> 1) * 8;   // 0..63
                int j  = wn * 48 + nt * 8 + 2 * tg + (e & 1);    // 0..191
                int nl = j / 3, d = j - nl * 3;
                sm[nl * OSTR + Cl * 3 + d] = acc[mt][nt][e] * ALPHA;
            }
        }
    }
    __syncthreads();
#pragma unroll
    for (int i = 0; i < 12; i++) {
        int idx = i * NTHREADS + tid;              // 3072 float4s
        int nl = idx / 48, f4 = idx % 48;
        int node = nodes_s[nl];
        if (node >= 0) {
            float4 v = *(const float4*)(sm + nl * OSTR + f4 * 4);
            *(float4*)(out + (size_t)node * (OUTC * MD) + c0 * 3 + f4 * 4) = v;
        }
    }
}

// --------- entry point ----------
extern "C" void kernel_launch(void* const* d_in, const int* in_sizes, int n_in,
                              void* d_out, int out_size)
{
    const float* t     = (const float*)d_in[0];   // [B, IN, M]
    const float* attrs = (const float*)d_in[1];   // [B, Z]
    const float* W     = (const float*)d_in[2];   // [Z, OUT, IN]
    float* out = (float*)d_out;                   // [B, OUT, M]

    k_classify<<<16, 512>>>(attrs);
    k_scan<<<1, 1024>>>();
    k_scatter<<<16, 512>>>();

    cudaFuncSetAttribute(k_pack, cudaFuncAttributeMaxDynamicSharedMemorySize, PACK_SMEM);
    k_pack<<<dim3(TILES + 160, 8), 256, PACK_SMEM>>>(t, W);

    cudaFuncSetAttribute(k_gemm, cudaFuncAttributeMaxDynamicSharedMemorySize, GEMM_SMEM);
    k_gemm<<<dim3(TILES, OUTC / CT), NTHREADS, GEMM_SMEM>>>(out);
}

// round 14
// speedup vs baseline: 1.0490x; 1.0490x over previous
#include <cuda_runtime.h>
#include <cuda_fp16.h>
#include <cstdint>

#define B_NODES 8192
#define ZS      10
#define INC     512
#define OUTC    512
#define MD      3
#define ALPHA   0.04419417382415922f   // 1/sqrt(512)

#define NT      64
#define NCOLS   (NT*MD)                // 192
#define CT      64                     // C tile (2 CTAs/SM)
#define KT      64                     // k halves per stage
#define KSTAGES (INC/KT)               // 8
#define NSLOTS  3
#define NTHREADS 256
#define TILES   138

#define A_BYTES     (CT*KT*2)          // 8192  (64 rows x 128B)
#define B_BYTES     (NCOLS*KT*2)       // 24576 (192 rows x 128B)
#define STAGE_BYTES (A_BYTES+B_BYTES)  // 32768
#define GEMM_SMEM   (NSLOTS*STAGE_BYTES) // 98304
#define OSTR 196                       // epilogue smem row stride (floats)

#define PKC  32                        // pack k-chunk (16 chunks per tile)
#define SHB2 104                       // pack smem row stride (halves; 96 data + 8 pad)
#define PACK_SMEM (NT*SHB2*2)          // 13312

// --------- scratch ----------
__device__ int g_tilez[TILES];
__device__ int g_psorted[TILES * NT];
__device__ int g_species[B_NODES];
__device__ int g_cursor[ZS];
__device__ __half Wh[(size_t)ZS * OUTC * INC];       // [z][c][k] fp16
__device__ __half Bh[(size_t)TILES * NCOLS * INC];   // [tile][n][k] fp16

// --------- helpers ----------
__device__ __forceinline__ void cpa16(void* dst, const void* src) {
    uint32_t d = (uint32_t)__cvta_generic_to_shared(dst);
    asm volatile("cp.async.cg.shared.global [%0], [%1], 16;" :: "r"(d), "l"(src) : "memory");
}
#define LDSM_X4(r, a) \
    asm volatile("ldmatrix.sync.aligned.m8n8.x4.shared.b16 {%0,%1,%2,%3}, [%4];" \
        : "=r"((r)[0]), "=r"((r)[1]), "=r"((r)[2]), "=r"((r)[3]) : "r"(a))

__device__ __forceinline__ void mma_f16(float* c, const uint32_t* a, const uint32_t* b) {
    asm volatile(
        "mma.sync.aligned.m16n8k16.row.col.f32.f16.f16.f32 "
        "{%0,%1,%2,%3}, {%4,%5,%6,%7}, {%8,%9}, {%0,%1,%2,%3};"
        : "+f"(c[0]), "+f"(c[1]), "+f"(c[2]), "+f"(c[3])
        : "r"(a[0]), "r"(a[1]), "r"(a[2]), "r"(a[3]), "r"(b[0]), "r"(b[1]));
}

// --------- prep stage 1: classify (16 blocks, coalesced) ----------
__global__ __launch_bounds__(512)
void k_classify(const float* __restrict__ attrs)
{
    __shared__ float buf[512 * ZS];
    const int tid = threadIdx.x;
    const float4* src = (const float4*)attrs + (size_t)blockIdx.x * 1280;
    float4* d = (float4*)buf;
#pragma unroll
    for (int i = 0; i < 3; i++) {
        int idx = i * 512 + tid;
        if (idx < 1280) d[idx] = src[idx];
    }
    __syncthreads();
    int s = 0;
#pragma unroll
    for (int z = 0; z < ZS; z++)
        s = (buf[tid * ZS + z] > 0.5f) ? z : s;
    g_species[blockIdx.x * 512 + tid] = s;
}

// --------- prep stage 2: hist + scan + tile table + sentinel fill ----------
__global__ __launch_bounds__(1024)
void k_scan()
{
    __shared__ int hist[ZS];
    const int tid = threadIdx.x;
    const int lane = tid & 31;
    if (tid < ZS) hist[tid] = 0;
    __syncthreads();
#pragma unroll
    for (int j = 0; j < 8; j++) {
        int s = g_species[j * 1024 + tid];
        unsigned m = __match_any_sync(0xffffffffu, s);
        if (lane == __ffs(m) - 1) atomicAdd(&hist[s], __popc(m));
    }
    __syncthreads();
    if (tid == 0) {
        int acc = 0;
        for (int z = 0; z < ZS; z++) {
            g_cursor[z] = acc;
            int tiles = (hist[z] + NT - 1) / NT;
            for (int ti = 0; ti < tiles; ti++) g_tilez[acc / NT + ti] = z;
            acc += tiles * NT;
        }
        for (int ti = acc / NT; ti < TILES; ti++) g_tilez[ti] = -1;
    }
    for (int i = tid; i < TILES * NT; i += 1024) g_psorted[i] = -1;
}

// --------- prep stage 3: scatter (16 blocks, hierarchical rank) ----------
__global__ __launch_bounds__(512)
void k_scatter()
{
    __shared__ int blkcnt[ZS], blkbase[ZS];
    const int tid = threadIdx.x;
    const int lane = tid & 31;
    if (tid < ZS) blkcnt[tid] = 0;
    __syncthreads();

    const int b = blockIdx.x * 512 + tid;
    const int s = g_species[b];
    unsigned m = __match_any_sync(0xffffffffu, s);
    int leader = __ffs(m) - 1;
    int gbase = 0;
    if (lane == leader) gbase = atomicAdd(&blkcnt[s], __popc(m));
    gbase = __shfl_sync(m, gbase, leader);
    const int rank = gbase + __popc(m & ((1u << lane) - 1));
    __syncthreads();

    if (tid < ZS && blkcnt[tid] > 0)
        blkbase[tid] = atomicAdd(&g_cursor[tid], blkcnt[tid]);
    __syncthreads();

    g_psorted[blkbase[s] + rank] = b;
}

// --------- fused pack: Bh (gather/convert/transpose, fp16 staging) + Wh ----------
// grid: x = TILES tile-blocks then 80 W-blocks; y = 16 k-chunks
__global__ void k_pack(const float* __restrict__ t, const float* __restrict__ W) {
    int bx = blockIdx.x;
    int tid = threadIdx.x;

    if (bx >= TILES) {
        // ---- W -> fp16 chunk ----
        int c = (bx - TILES) * 16 + blockIdx.y;          // 0..1279
        size_t i = ((size_t)c * 256 + tid) * 8;
        float4 v0 = *(const float4*)(W + i);
        float4 v1 = *(const float4*)(W + i + 4);
        __half2 h[4];
        h[0] = __floats2half2_rn(v0.x, v0.y);
        h[1] = __floats2half2_rn(v0.z, v0.w);
        h[2] = __floats2half2_rn(v1.x, v1.y);
        h[3] = __floats2half2_rn(v1.z, v1.w);
        *(uint4*)(Wh + i) = *(uint4*)h;
        return;
    }

    int tile = bx;
    if (g_tilez[tile] < 0) return;
    int kc = blockIdx.y;                     // 32-k chunk (16 per tile)
    extern __shared__ __half sh2[];          // [64 nodes][104] halves
#pragma unroll
    for (int i = 0; i < 6; i++) {
        int idx = i * 256 + tid;             // 1536 float4s (64 nodes x 24)
        int nl = idx / 24, f4 = idx % 24;
        int node = g_psorted[tile * NT + nl];
        float4 v = make_float4(0.f, 0.f, 0.f, 0.f);
        if (node >= 0)
            v = *(const float4*)(t + (size_t)node * (INC * MD) + kc * (PKC * MD) + f4 * 4);
        __half2 p[2];
        p[0] = __floats2half2_rn(v.x, v.y);
        p[1] = __floats2half2_rn(v.z, v.w);
        *(uint2*)(sh2 + nl * SHB2 + f4 * 4) = *(uint2*)p;
    }
    __syncthreads();
    __half* dst = Bh + (size_t)tile * NCOLS * INC + kc * PKC;
#pragma unroll
    for (int i = 0; i < 6; i++) {
        int idx = i * 256 + tid;             // 1536 = 192 n-rows x 8 quad-groups
        int n = idx >> 3, kq = idx & 7;
        int nl = n / 3, d = n % 3;
        __half q[4];
        q[0] = sh2[nl * SHB2 + (kq * 4 + 0) * 3 + d];
        q[1] = sh2[nl * SHB2 + (kq * 4 + 1) * 3 + d];
        q[2] = sh2[nl * SHB2 + (kq * 4 + 2) * 3 + d];
        q[3] = sh2[nl * SHB2 + (kq * 4 + 3) * 3 + d];
        *(uint2*)(dst + (size_t)n * INC + kq * 4) = *(uint2*)q;
    }
}

// --------- GEMM: CT=64, 256 thr, 2 CTAs/SM, cp.async ring + ldmatrix + fp16 mma ----------
__global__ __launch_bounds__(NTHREADS, 2)
void k_gemm(float* __restrict__ out)
{
    const int tile = blockIdx.x;
    const int z = g_tilez[tile];
    if (z < 0) return;
    const int c0 = blockIdx.y * CT;

    extern __shared__ float sm[];
    char* smc = (char*)sm;
    __shared__ int nodes_s[NT];

    const int tid = threadIdx.x;
    if (tid < NT) nodes_s[tid] = g_psorted[tile * NT + tid];

    const int lane = tid & 31;
    const int wid  = tid >> 5;
    const int wm   = wid & 1;              // 2 M groups (32 rows)
    const int wn   = wid >> 1;             // 4 N groups (48 cols)
    const int g    = lane >> 2;
    const int tg   = lane & 3;

    const __half* abase = Wh + ((size_t)z * OUTC + c0) * INC;
    const __half* bbase = Bh + (size_t)tile * NCOLS * INC;

    // per stage: A 512 16B-chunks (64 rows x 8), B 1536 (192 rows x 8)
    auto issue = [&](int s) {
        char* ab = smc + (s % NSLOTS) * STAGE_BYTES;
        const __half* asrc = abase + s * KT;
#pragma unroll
        for (int i = 0; i < 2; i++) {
            int idx = i * NTHREADS + tid;
            int m = idx >> 3, c = idx & 7;
            cpa16(ab + m * 128 + ((c ^ (m & 7)) << 4),
                  asrc + (size_t)m * INC + c * 8);
        }
        char* bb = ab + A_BYTES;
        const __half* bsrc = bbase + s * KT;
#pragma unroll
        for (int i = 0; i < 6; i++) {
            int idx = i * NTHREADS + tid;
            int n = idx >> 3, c = idx & 7;
            cpa16(bb + n * 128 + ((c ^ (n & 7)) << 4),
                  bsrc + (size_t)n * INC + c * 8);
        }
    };

    issue(0); asm volatile("cp.async.commit_group;" ::: "memory");
    issue(1); asm volatile("cp.async.commit_group;" ::: "memory");

    // ---- per-lane ldmatrix addressing ----
    const int mi = lane >> 3;
    const int mr = lane & 7;
    uint32_t aoff[2], a7[2];
#pragma unroll
    for (int mt = 0; mt < 2; mt++) {
        int m = wm * 32 + mt * 16 + (mi & 1) * 8 + mr;
        aoff[mt] = (uint32_t)m * 128;
        a7[mt] = (uint32_t)(m & 7);
    }
    const uint32_t akc = (uint32_t)(mi >> 1);
    uint32_t boff[3], b7[3];
#pragma unroll
    for (int p = 0; p < 3; p++) {
        int n = wn * 48 + p * 16 + (mi >> 1) * 8 + mr;
        boff[p] = (uint32_t)n * 128;
        b7[p] = (uint32_t)(n & 7);
    }
    const uint32_t bkc = (uint32_t)(mi & 1);
    const uint32_t smbase = (uint32_t)__cvta_generic_to_shared(sm);

    float acc[2][6][4];
#pragma unroll
    for (int i = 0; i < 2; i++)
#pragma unroll
        for (int j = 0; j < 6; j++)
#pragma unroll
            for (int e = 0; e < 4; e++) acc[i][j][e] = 0.f;

    for (int s = 0; s < KSTAGES; s++) {
        asm volatile("cp.async.wait_group 1;" ::: "memory");
        __syncthreads();
        if (s + 2 < KSTAGES) issue(s + 2);
        asm volatile("cp.async.commit_group;" ::: "memory");

        const uint32_t sA = smbase + (s % NSLOTS) * STAGE_BYTES;
        const uint32_t sB = sA + A_BYTES;
#pragma unroll
        for (int kc = 0; kc < 4; kc++) {
            uint32_t a[2][4];
#pragma unroll
            for (int mt = 0; mt < 2; mt++)
                LDSM_X4(a[mt], sA + aoff[mt] + (((((uint32_t)kc << 1) + akc) ^ a7[mt]) << 4));
            uint32_t b[3][4];
#pragma unroll
            for (int p = 0; p < 3; p++)
                LDSM_X4(b[p], sB + boff[p] + (((((uint32_t)kc << 1) + bkc) ^ b7[p]) << 4));
#pragma unroll
            for (int mt = 0; mt < 2; mt++)
#pragma unroll
                for (int nt = 0; nt < 6; nt++)
                    mma_f16(acc[mt][nt], a[mt], b[nt >> 1] + (nt & 1) * 2);
        }
    }

    // ---- epilogue: acc -> smem [node][C*3+d] (64x196 floats) -> coalesced out ----
    __syncthreads();
#pragma unroll
    for (int mt = 0; mt < 2; mt++) {
#pragma unroll
        for (int nt = 0; nt < 6; nt++) {
#pragma unroll
            for (int e = 0; e < 4; e++) {
                int Cl = wm * 32 + mt * 16 + g + (e >> 1) * 8;   // 0..63
                int j  = wn * 48 + nt * 8 + 2 * tg + (e & 1);    // 0..191
                int nl = j / 3, d = j - nl * 3;
                sm[nl * OSTR + Cl * 3 + d] = acc[mt][nt][e] * ALPHA;
            }
        }
    }
    __syncthreads();
#pragma unroll
    for (int i = 0; i < 12; i++) {
        int idx = i * NTHREADS + tid;              // 3072 float4s
        int nl = idx / 48, f4 = idx % 48;
        int node = nodes_s[nl];
        if (node >= 0) {
            float4 v = *(const float4*)(sm + nl * OSTR + f4 * 4);
            *(float4*)(out + (size_t)node * (OUTC * MD) + c0 * 3 + f4 * 4) = v;
        }
    }
}

// --------- entry point ----------
extern "C" void kernel_launch(void* const* d_in, const int* in_sizes, int n_in,
                              void* d_out, int out_size)
{
    const float* t     = (const float*)d_in[0];   // [B, IN, M]
    const float* attrs = (const float*)d_in[1];   // [B, Z]
    const float* W     = (const float*)d_in[2];   // [Z, OUT, IN]
    float* out = (float*)d_out;                   // [B, OUT, M]

    k_classify<<<16, 512>>>(attrs);
    k_scan<<<1, 1024>>>();
    k_scatter<<<16, 512>>>();

    cudaFuncSetAttribute(k_pack, cudaFuncAttributeMaxDynamicSharedMemorySize, PACK_SMEM);
    k_pack<<<dim3(TILES + 80, 16), 256, PACK_SMEM>>>(t, W);

    cudaFuncSetAttribute(k_gemm, cudaFuncAttributeMaxDynamicSharedMemorySize, GEMM_SMEM);
    k_gemm<<<dim3(TILES, OUTC / CT), NTHREADS, GEMM_SMEM>>>(out);
}